// round 13
// baseline (speedup 1.0000x reference)
#include <cuda_runtime.h>

// Problem constants
#define B_  64
#define H_  1024
#define I_  1024
#define BH  (B_ * H_)          // 65536
#define BHI ((size_t)BH * I_)  // 67108864
#define ROWS 4                 // rows per block = pairs per block

__device__ __forceinline__ float tanh_fast(float x) {
    float r;
    asm("tanh.approx.f32 %0, %1;" : "=f"(r) : "f"(x));
    return r;
}

// ---------------------------------------------------------------------------
// Pair-per-row fused kernel. Block = 256 threads = 8 warps = 4 pairs.
// Pair p (warps 2p, 2p+1) owns row bh0+p; its 64 threads each own 4 float4
// column chunks (ct + 64k).
//   - stream Z/F chunks issued FIRST (32 regs, proven mandatory for overlap)
//   - GEMV: per-thread dot over 4 chunks, 5-step butterfly per warp,
//     then ONE named barrier over the 2-warp pair (not 8-warp block):
//     each warp's stores wait on a single partner, not on 7 others
//   - epilogue redundantly in all 64 lanes of the pair (no broadcasts)
//   - x chunks reloaded from L1 (hot) in the store phase
// ---------------------------------------------------------------------------
__global__ void __launch_bounds__(256, 4) fused_kernel(
    const float4* __restrict__ x4,     // [B, I/4]
    const float*  __restrict__ hidden_prev,
    const float4* __restrict__ Z,      // [BH, I/4]
    const float4* __restrict__ F,
    const float*  __restrict__ wz_state,
    const float*  __restrict__ wf_state,
    const float*  __restrict__ bz_state,
    const float*  __restrict__ bf_state,
    const float4* __restrict__ wmz4,   // [H, I/4]
    const float4* __restrict__ wmf4,
    const float*  __restrict__ wv_z,   // [H]
    const float*  __restrict__ wv_f,
    const float*  __restrict__ bias_z,
    const float*  __restrict__ bias_f,
    float*  __restrict__ out_cell,     // [B, H]
    float4* __restrict__ Zo,
    float4* __restrict__ Fo,
    float*  __restrict__ out_wz,
    float*  __restrict__ out_wf,
    float*  __restrict__ out_bz,
    float*  __restrict__ out_bf)
{
    __shared__ float red[ROWS][2][2];   // [pair][warp-in-pair][gate]

    const int bh0  = blockIdx.x * ROWS;
    const int b    = bh0 >> 10;
    const int h0   = bh0 & (H_ - 1);
    const int t    = threadIdx.x;
    const int wid  = t >> 5;
    const int lane = t & 31;
    const int pair = wid >> 1;          // 0..3
    const int wip  = wid & 1;           // warp-in-pair
    const int ct   = t & 63;            // column-thread within pair

    const int    row  = bh0 + pair;
    const int    h    = h0 + pair;
    const size_t rb   = (size_t)row << 8;     // float4 base of this row
    const size_t xb   = (size_t)b << 8;
    const size_t hb   = (size_t)h << 8;

    // ---- streaming loads: 4 Z + 4 F chunks per thread, issued first ----
    float4 zv[4], fv[4];
    #pragma unroll
    for (int k = 0; k < 4; ++k) {
        zv[k] = __ldcs(Z + rb + ct + k * 64);
        fv[k] = __ldcs(F + rb + ct + k * 64);
    }

    // ---- GEMV: per-thread dot over this thread's 4 column chunks ----
    float az = 0.f, af = 0.f;
    #pragma unroll
    for (int k = 0; k < 4; ++k) {
        const float4 xc  = __ldg(x4   + xb + ct + k * 64);
        const float4 wzc = __ldg(wmz4 + hb + ct + k * 64);
        const float4 wfc = __ldg(wmf4 + hb + ct + k * 64);
        az += xc.x * wzc.x + xc.y * wzc.y + xc.z * wzc.z + xc.w * wzc.w;
        af += xc.x * wfc.x + xc.y * wfc.y + xc.z * wfc.z + xc.w * wfc.w;
    }
    #pragma unroll
    for (int o = 16; o > 0; o >>= 1) {
        az += __shfl_xor_sync(0xffffffffu, az, o);
        af += __shfl_xor_sync(0xffffffffu, af, o);
    }
    if (lane == 0) {
        red[pair][wip][0] = az;
        red[pair][wip][1] = af;
    }

    // ---- named barrier over THIS PAIR only (64 threads) ----
    asm volatile("bar.sync %0, 64;" :: "r"(pair + 1) : "memory");

    // ---- epilogue: all 64 lanes of the pair, redundantly ----
    const float AZ = red[pair][0][0] + red[pair][1][0];
    const float AF = red[pair][0][1] + red[pair][1][1];

    const float hp   = hidden_prev[row];
    const float vz   = wv_z[h];
    const float vf   = wv_f[h];
    const float z    = tanh_fast(AZ + vz * hp + bias_z[h]);
    const float fpre = AF + vf * hp + bias_f[h];
    const float f    = 0.5f * tanh_fast(0.5f * fpre) + 0.5f;   // sigmoid

    const float zfc    = (1.f - f) * (1.f - z * z);
    const float fzc    = (hp - z) * (1.f - f) * f;
    const float common = f + zfc * vz + fzc * vf;

    if (wip == 0 && lane == 0) {       // single writer for small outputs
        out_cell[row] = hp * f + (1.f - f) * z;
        out_wz[row]   = hp * zfc + common * wz_state[row];
        out_wf[row]   = hp * fzc + common * wf_state[row];
        out_bz[row]   = zfc + common * bz_state[row];
        out_bf[row]   = fzc + common * bf_state[row];
    }

    // ---- store phase: x reloaded from L1 (hot); streaming stores ----
    #pragma unroll
    for (int k = 0; k < 4; ++k) {
        const float4 xc = __ldg(x4 + xb + ct + k * 64);

        float4 zo, fo;
        zo.x = common * zv[k].x + zfc * xc.x;
        zo.y = common * zv[k].y + zfc * xc.y;
        zo.z = common * zv[k].z + zfc * xc.z;
        zo.w = common * zv[k].w + zfc * xc.w;
        fo.x = common * fv[k].x + fzc * xc.x;
        fo.y = common * fv[k].y + fzc * xc.y;
        fo.z = common * fv[k].z + fzc * xc.z;
        fo.w = common * fv[k].w + fzc * xc.w;

        __stcs(Zo + rb + ct + k * 64, zo);
        __stcs(Fo + rb + ct + k * 64, fo);
    }
}

// ---------------------------------------------------------------------------
extern "C" void kernel_launch(void* const* d_in, const int* in_sizes, int n_in,
                              void* d_out, int out_size)
{
    const float* x           = (const float*)d_in[0];
    const float* hidden_prev = (const float*)d_in[1];
    const float* Z_state     = (const float*)d_in[2];
    const float* F_state     = (const float*)d_in[3];
    const float* wz_state    = (const float*)d_in[4];
    const float* wf_state    = (const float*)d_in[5];
    const float* bz_state    = (const float*)d_in[6];
    const float* bf_state    = (const float*)d_in[7];
    const float* wm_z        = (const float*)d_in[8];
    const float* wm_f        = (const float*)d_in[9];
    const float* wv_z        = (const float*)d_in[10];
    const float* wv_f        = (const float*)d_in[11];
    const float* bias_z      = (const float*)d_in[12];
    const float* bias_f      = (const float*)d_in[13];

    float* out = (float*)d_out;
    // Output tuple layout: new_cell, Z_new, F_new, wz_new, wf_new, bz_new, bf_new
    float* o_cell = out;
    float* o_Z    = out + BH;
    float* o_F    = o_Z + BHI;
    float* o_wz   = o_F + BHI;
    float* o_wf   = o_wz + BH;
    float* o_bz   = o_wf + BH;
    float* o_bf   = o_bz + BH;

    fused_kernel<<<BH / ROWS, 256>>>(
        (const float4*)x, hidden_prev,
        (const float4*)Z_state, (const float4*)F_state,
        wz_state, wf_state, bz_state, bf_state,
        (const float4*)wm_z, (const float4*)wm_f,
        wv_z, wv_f, bias_z, bias_f,
        o_cell, (float4*)o_Z, (float4*)o_F,
        o_wz, o_wf, o_bz, o_bf);
}

// round 14
// speedup vs baseline: 1.0090x; 1.0090x over previous
#include <cuda_runtime.h>

// Problem constants
#define B_  64
#define H_  1024
#define I_  1024
#define BH  (B_ * H_)          // 65536
#define BHI ((size_t)BH * I_)  // 67108864
#define ROWS 4                 // (b,h) rows per block; consecutive bh share b

// ---------------------------------------------------------------------------
// Fused kernel, 4 rows per 256-thread block, single barrier (R10, final):
//   - streaming Z/F loads for all 4 rows issued FIRST (8 float4 in flight;
//     overlap with the GEMV serial chain is mandatory — every variant that
//     deferred any stream loads (R6/R8/R11) or shrank the sync domain (R13)
//     regressed)
//   - gate GEMV partials for 4 rows vs one register x chunk, warp-shuffle
//     reduce, ONE __syncthreads
//   - warp-redundant epilogue in lanes 0..3; coef broadcast via shuffle
//   - warp 0's small outputs written AFTER the stream stores so its DRAM
//     stores issue in lockstep with the other warps
// ---------------------------------------------------------------------------
__global__ void __launch_bounds__(256, 4) fused_kernel(
    const float4* __restrict__ x4,     // [B, I/4]
    const float*  __restrict__ hidden_prev,
    const float4* __restrict__ Z,      // [BH, I/4]
    const float4* __restrict__ F,
    const float*  __restrict__ wz_state,
    const float*  __restrict__ wf_state,
    const float*  __restrict__ bz_state,
    const float*  __restrict__ bf_state,
    const float4* __restrict__ wmz4,   // [H, I/4]
    const float4* __restrict__ wmf4,
    const float*  __restrict__ wv_z,   // [H]
    const float*  __restrict__ wv_f,
    const float*  __restrict__ bias_z,
    const float*  __restrict__ bias_f,
    float*  __restrict__ out_cell,     // [B, H]
    float4* __restrict__ Zo,
    float4* __restrict__ Fo,
    float*  __restrict__ out_wz,
    float*  __restrict__ out_wf,
    float*  __restrict__ out_bz,
    float*  __restrict__ out_bf)
{
    __shared__ float red[8][2 * ROWS];   // [warp][r*2 + gate]

    const int bh0  = blockIdx.x * ROWS;
    const int b    = bh0 >> 10;
    const int h0   = bh0 & (H_ - 1);
    const int t    = threadIdx.x;
    const int wid  = t >> 5;
    const int lane = t & 31;

    const size_t row0 = (size_t)bh0 << 8;   // float4 offset of first row

    // ---- streaming loads for all 4 rows, issued first (touch-once) ----
    float4 zv[ROWS], fv[ROWS];
    #pragma unroll
    for (int r = 0; r < ROWS; ++r) {
        zv[r] = __ldcs(Z + row0 + (size_t)(r << 8) + t);
        fv[r] = __ldcs(F + row0 + (size_t)(r << 8) + t);
    }

    // ---- GEMV partials: one x chunk, 4 wm_z/wm_f row chunks (L2-hot) ----
    const float4 xv = __ldg(x4 + ((size_t)b << 8) + t);
    float pz[ROWS], pf[ROWS];
    #pragma unroll
    for (int r = 0; r < ROWS; ++r) {
        const float4 wzv = __ldg(wmz4 + ((size_t)(h0 + r) << 8) + t);
        const float4 wfv = __ldg(wmf4 + ((size_t)(h0 + r) << 8) + t);
        pz[r] = xv.x * wzv.x + xv.y * wzv.y + xv.z * wzv.z + xv.w * wzv.w;
        pf[r] = xv.x * wfv.x + xv.y * wfv.y + xv.z * wfv.z + xv.w * wfv.w;
    }
    #pragma unroll
    for (int o = 16; o > 0; o >>= 1) {
        #pragma unroll
        for (int r = 0; r < ROWS; ++r) {
            pz[r] += __shfl_xor_sync(0xffffffffu, pz[r], o);
            pf[r] += __shfl_xor_sync(0xffffffffu, pf[r], o);
        }
    }
    if (lane == 0) {
        #pragma unroll
        for (int r = 0; r < ROWS; ++r) {
            red[wid][r * 2]     = pz[r];
            red[wid][r * 2 + 1] = pf[r];
        }
    }
    __syncthreads();   // the ONLY barrier

    // ---- epilogue: redundantly in lanes 0..3 of every warp ----
    float common = 0.f, zfc = 0.f, fzc = 0.f;
    float hp = 0.f, zz = 0.f, ff = 0.f;
    if (lane < ROWS) {
        const int bh = bh0 + lane;
        const int h  = h0 + lane;

        float AZ = 0.f, AF = 0.f;
        #pragma unroll
        for (int w = 0; w < 8; ++w) {
            AZ += red[w][lane * 2];
            AF += red[w][lane * 2 + 1];
        }

        hp = hidden_prev[bh];
        const float vz   = wv_z[h];
        const float vf   = wv_f[h];
        zz = tanhf(AZ + vz * hp + bias_z[h]);
        const float fpre = AF + vf * hp + bias_f[h];
        ff = 1.f / (1.f + expf(-fpre));

        zfc    = (1.f - ff) * (1.f - zz * zz);
        fzc    = (hp - zz) * (1.f - ff) * ff;
        common = ff + zfc * vz + fzc * vf;
    }

    // ---- streaming FMA + stores; coef broadcast via intra-warp shuffle ----
    #pragma unroll
    for (int r = 0; r < ROWS; ++r) {
        const float c   = __shfl_sync(0xffffffffu, common, r);
        const float czf = __shfl_sync(0xffffffffu, zfc, r);
        const float cfz = __shfl_sync(0xffffffffu, fzc, r);

        float4 zo, fo;
        zo.x = c * zv[r].x + czf * xv.x;
        zo.y = c * zv[r].y + czf * xv.y;
        zo.z = c * zv[r].z + czf * xv.z;
        zo.w = c * zv[r].w + czf * xv.w;
        fo.x = c * fv[r].x + cfz * xv.x;
        fo.y = c * fv[r].y + cfz * xv.y;
        fo.z = c * fv[r].z + cfz * xv.z;
        fo.w = c * fv[r].w + cfz * xv.w;

        const size_t off = row0 + (size_t)(r << 8) + t;
        __stcs(Zo + off, zo);
        __stcs(Fo + off, fo);
    }

    // ---- small outputs last (warp 0 only) so its big stores went first ----
    if (wid == 0 && lane < ROWS) {
        const int bh = bh0 + lane;
        out_cell[bh] = hp * ff + (1.f - ff) * zz;
        out_wz[bh]   = hp * zfc + common * wz_state[bh];
        out_wf[bh]   = hp * fzc + common * wf_state[bh];
        out_bz[bh]   = zfc + common * bz_state[bh];
        out_bf[bh]   = fzc + common * bf_state[bh];
    }
}

// ---------------------------------------------------------------------------
extern "C" void kernel_launch(void* const* d_in, const int* in_sizes, int n_in,
                              void* d_out, int out_size)
{
    const float* x           = (const float*)d_in[0];
    const float* hidden_prev = (const float*)d_in[1];
    const float* Z_state     = (const float*)d_in[2];
    const float* F_state     = (const float*)d_in[3];
    const float* wz_state    = (const float*)d_in[4];
    const float* wf_state    = (const float*)d_in[5];
    const float* bz_state    = (const float*)d_in[6];
    const float* bf_state    = (const float*)d_in[7];
    const float* wm_z        = (const float*)d_in[8];
    const float* wm_f        = (const float*)d_in[9];
    const float* wv_z        = (const float*)d_in[10];
    const float* wv_f        = (const float*)d_in[11];
    const float* bias_z      = (const float*)d_in[12];
    const float* bias_f      = (const float*)d_in[13];

    float* out = (float*)d_out;
    // Output tuple layout: new_cell, Z_new, F_new, wz_new, wf_new, bz_new, bf_new
    float* o_cell = out;
    float* o_Z    = out + BH;
    float* o_F    = o_Z + BHI;
    float* o_wz   = o_F + BHI;
    float* o_wf   = o_wz + BH;
    float* o_bz   = o_wf + BH;
    float* o_bf   = o_bz + BH;

    fused_kernel<<<BH / ROWS, 256>>>(
        (const float4*)x, hidden_prev,
        (const float4*)Z_state, (const float4*)F_state,
        wz_state, wf_state, bz_state, bf_state,
        (const float4*)wm_z, (const float4*)wm_f,
        wv_z, wv_f, bias_z, bias_f,
        o_cell, (float4*)o_Z, (float4*)o_F,
        o_wz, o_wf, o_bz, o_bf);
}

// round 15
// speedup vs baseline: 1.0131x; 1.0041x over previous
#include <cuda_runtime.h>

// Problem constants
#define B_  64
#define H_  1024
#define I_  1024
#define BH  (B_ * H_)          // 65536
#define BHI ((size_t)BH * I_)  // 67108864
#define ROWS 4                 // (b,h) rows per block; consecutive bh share b

// ---------------------------------------------------------------------------
// FINAL: fused RTRL quasi-LSTM kernel, 4 rows per 256-thread block.
// Converged at the mixed read/write DRAM roofline: 1.084 GB compulsory
// traffic at ~7.0 TB/s effective (above the best pure-streamer rate measured
// on this GB300), kernel 154.9 us.
//
// Design facts established over 14 rounds:
//   - streaming Z/F loads for all 4 rows issued FIRST (8 float4 in flight;
//     overlap with the GEMV serial chain is mandatory — deferring any stream
//     loads (R6/R8/R11) or shrinking the sync domain (R13) regressed 4-16us)
//   - gate GEMV partials for 4 rows vs one register x chunk (wm rows are
//     L2-resident, 8 MB), warp-shuffle reduce, ONE __syncthreads
//   - warp-redundant epilogue in lanes 0..3 (no second barrier); coef
//     broadcast via intra-warp shuffle
//   - warp 0 writes the five small outputs after its stream stores
//   - 64 regs / 4 CTAs/SM: the sweet spot (raising occupancy by shedding
//     stream registers always cost more overlap than it bought)
// ---------------------------------------------------------------------------
__global__ void __launch_bounds__(256, 4) fused_kernel(
    const float4* __restrict__ x4,     // [B, I/4]
    const float*  __restrict__ hidden_prev,
    const float4* __restrict__ Z,      // [BH, I/4]
    const float4* __restrict__ F,
    const float*  __restrict__ wz_state,
    const float*  __restrict__ wf_state,
    const float*  __restrict__ bz_state,
    const float*  __restrict__ bf_state,
    const float4* __restrict__ wmz4,   // [H, I/4]
    const float4* __restrict__ wmf4,
    const float*  __restrict__ wv_z,   // [H]
    const float*  __restrict__ wv_f,
    const float*  __restrict__ bias_z,
    const float*  __restrict__ bias_f,
    float*  __restrict__ out_cell,     // [B, H]
    float4* __restrict__ Zo,
    float4* __restrict__ Fo,
    float*  __restrict__ out_wz,
    float*  __restrict__ out_wf,
    float*  __restrict__ out_bz,
    float*  __restrict__ out_bf)
{
    __shared__ float red[8][2 * ROWS];   // [warp][r*2 + gate]

    const int bh0  = blockIdx.x * ROWS;
    const int b    = bh0 >> 10;
    const int h0   = bh0 & (H_ - 1);
    const int t    = threadIdx.x;
    const int wid  = t >> 5;
    const int lane = t & 31;

    const size_t row0 = (size_t)bh0 << 8;   // float4 offset of first row

    // ---- streaming loads for all 4 rows, issued first (touch-once) ----
    float4 zv[ROWS], fv[ROWS];
    #pragma unroll
    for (int r = 0; r < ROWS; ++r) {
        zv[r] = __ldcs(Z + row0 + (size_t)(r << 8) + t);
        fv[r] = __ldcs(F + row0 + (size_t)(r << 8) + t);
    }

    // ---- GEMV partials: one x chunk, 4 wm_z/wm_f row chunks (L2-hot) ----
    const float4 xv = __ldg(x4 + ((size_t)b << 8) + t);
    float pz[ROWS], pf[ROWS];
    #pragma unroll
    for (int r = 0; r < ROWS; ++r) {
        const float4 wzv = __ldg(wmz4 + ((size_t)(h0 + r) << 8) + t);
        const float4 wfv = __ldg(wmf4 + ((size_t)(h0 + r) << 8) + t);
        pz[r] = xv.x * wzv.x + xv.y * wzv.y + xv.z * wzv.z + xv.w * wzv.w;
        pf[r] = xv.x * wfv.x + xv.y * wfv.y + xv.z * wfv.z + xv.w * wfv.w;
    }
    #pragma unroll
    for (int o = 16; o > 0; o >>= 1) {
        #pragma unroll
        for (int r = 0; r < ROWS; ++r) {
            pz[r] += __shfl_xor_sync(0xffffffffu, pz[r], o);
            pf[r] += __shfl_xor_sync(0xffffffffu, pf[r], o);
        }
    }
    if (lane == 0) {
        #pragma unroll
        for (int r = 0; r < ROWS; ++r) {
            red[wid][r * 2]     = pz[r];
            red[wid][r * 2 + 1] = pf[r];
        }
    }
    __syncthreads();   // the ONLY barrier

    // ---- epilogue: redundantly in lanes 0..3 of every warp ----
    float common = 0.f, zfc = 0.f, fzc = 0.f;
    float hp = 0.f, zz = 0.f, ff = 0.f;
    if (lane < ROWS) {
        const int bh = bh0 + lane;
        const int h  = h0 + lane;

        float AZ = 0.f, AF = 0.f;
        #pragma unroll
        for (int w = 0; w < 8; ++w) {
            AZ += red[w][lane * 2];
            AF += red[w][lane * 2 + 1];
        }

        hp = hidden_prev[bh];
        const float vz   = wv_z[h];
        const float vf   = wv_f[h];
        zz = tanhf(AZ + vz * hp + bias_z[h]);
        const float fpre = AF + vf * hp + bias_f[h];
        ff = 1.f / (1.f + expf(-fpre));

        zfc    = (1.f - ff) * (1.f - zz * zz);
        fzc    = (hp - zz) * (1.f - ff) * ff;
        common = ff + zfc * vz + fzc * vf;
    }

    // ---- streaming FMA + stores; coef broadcast via intra-warp shuffle ----
    #pragma unroll
    for (int r = 0; r < ROWS; ++r) {
        const float c   = __shfl_sync(0xffffffffu, common, r);
        const float czf = __shfl_sync(0xffffffffu, zfc, r);
        const float cfz = __shfl_sync(0xffffffffu, fzc, r);

        float4 zo, fo;
        zo.x = c * zv[r].x + czf * xv.x;
        zo.y = c * zv[r].y + czf * xv.y;
        zo.z = c * zv[r].z + czf * xv.z;
        zo.w = c * zv[r].w + czf * xv.w;
        fo.x = c * fv[r].x + cfz * xv.x;
        fo.y = c * fv[r].y + cfz * xv.y;
        fo.z = c * fv[r].z + cfz * xv.z;
        fo.w = c * fv[r].w + cfz * xv.w;

        const size_t off = row0 + (size_t)(r << 8) + t;
        __stcs(Zo + off, zo);
        __stcs(Fo + off, fo);
    }

    // ---- small outputs last (warp 0 only) so its big stores went first ----
    if (wid == 0 && lane < ROWS) {
        const int bh = bh0 + lane;
        out_cell[bh] = hp * ff + (1.f - ff) * zz;
        out_wz[bh]   = hp * zfc + common * wz_state[bh];
        out_wf[bh]   = hp * fzc + common * wf_state[bh];
        out_bz[bh]   = zfc + common * bz_state[bh];
        out_bf[bh]   = fzc + common * bf_state[bh];
    }
}

// ---------------------------------------------------------------------------
extern "C" void kernel_launch(void* const* d_in, const int* in_sizes, int n_in,
                              void* d_out, int out_size)
{
    const float* x           = (const float*)d_in[0];
    const float* hidden_prev = (const float*)d_in[1];
    const float* Z_state     = (const float*)d_in[2];
    const float* F_state     = (const float*)d_in[3];
    const float* wz_state    = (const float*)d_in[4];
    const float* wf_state    = (const float*)d_in[5];
    const float* bz_state    = (const float*)d_in[6];
    const float* bf_state    = (const float*)d_in[7];
    const float* wm_z        = (const float*)d_in[8];
    const float* wm_f        = (const float*)d_in[9];
    const float* wv_z        = (const float*)d_in[10];
    const float* wv_f        = (const float*)d_in[11];
    const float* bias_z      = (const float*)d_in[12];
    const float* bias_f      = (const float*)d_in[13];

    float* out = (float*)d_out;
    // Output tuple layout: new_cell, Z_new, F_new, wz_new, wf_new, bz_new, bf_new
    float* o_cell = out;
    float* o_Z    = out + BH;
    float* o_F    = o_Z + BHI;
    float* o_wz   = o_F + BHI;
    float* o_wf   = o_wz + BH;
    float* o_bz   = o_wf + BH;
    float* o_bf   = o_bz + BH;

    fused_kernel<<<BH / ROWS, 256>>>(
        (const float4*)x, hidden_prev,
        (const float4*)Z_state, (const float4*)F_state,
        wz_state, wf_state, bz_state, bf_state,
        (const float4*)wm_z, (const float4*)wm_f,
        wv_z, wv_f, bias_z, bias_f,
        o_cell, (float4*)o_Z, (float4*)o_F,
        o_wz, o_wf, o_bz, o_bf);
}